// round 1
// baseline (speedup 1.0000x reference)
#include <cuda_runtime.h>
#include <math.h>

#define D_MODEL 1024
#define NH      16
#define DH      64
#define B_      2
#define S_      2048
#define M_TOK   (B_ * S_)          // 4096 token rows
#define ATT_SCALE 0.125f           // 1/sqrt(64)

// -------- scratch (allocation-free: __device__ globals) --------
__device__ float g_Q[M_TOK * D_MODEL];
__device__ float g_K[M_TOK * D_MODEL];
__device__ float g_V[M_TOK * D_MODEL];
__device__ float g_A[M_TOK * D_MODEL];

// ============================================================================
// NT GEMM: C[m][n] = sum_k A[m][k] * W[n][k]
// M = 4096, N = K = 1024. 64x64 block tile, TK=16, 256 threads, 4x4 per thread.
// HEAD_LAYOUT=true writes C into [B, H, S, Dh] head-major layout
// (m = b*S+s, n = h*64+d  ->  ((b*H+h)*S+s)*64+d), else plain row-major.
// ============================================================================
template <bool HEAD_LAYOUT>
__global__ __launch_bounds__(256) void gemm_nt_kernel(
    const float* __restrict__ A,
    const float* __restrict__ W,
    float* __restrict__ C)
{
    __shared__ float As[16][64];   // k-major
    __shared__ float Ws[16][64];   // k-major

    const int tid = threadIdx.x;
    const int tx  = tid & 15;      // 0..15 -> n micro
    const int ty  = tid >> 4;      // 0..15 -> m micro
    const int m0  = blockIdx.y * 64;
    const int n0  = blockIdx.x * 64;

    const int lrow = tid >> 2;        // 0..63 : tile row being loaded
    const int lk4  = (tid & 3) * 4;   // 0,4,8,12 : k offset (float4)

    float acc[4][4];
#pragma unroll
    for (int i = 0; i < 4; i++)
#pragma unroll
        for (int j = 0; j < 4; j++) acc[i][j] = 0.f;

    const float* aptr = A + (size_t)(m0 + lrow) * D_MODEL + lk4;
    const float* wptr = W + (size_t)(n0 + lrow) * D_MODEL + lk4;

    for (int k0 = 0; k0 < D_MODEL; k0 += 16) {
        float4 a4 = *(const float4*)(aptr + k0);
        float4 w4 = *(const float4*)(wptr + k0);
        __syncthreads();
        As[lk4 + 0][lrow] = a4.x; As[lk4 + 1][lrow] = a4.y;
        As[lk4 + 2][lrow] = a4.z; As[lk4 + 3][lrow] = a4.w;
        Ws[lk4 + 0][lrow] = w4.x; Ws[lk4 + 1][lrow] = w4.y;
        Ws[lk4 + 2][lrow] = w4.z; Ws[lk4 + 3][lrow] = w4.w;
        __syncthreads();

#pragma unroll
        for (int kk = 0; kk < 16; kk++) {
            float4 av = *(const float4*)&As[kk][ty * 4];
            float4 wv = *(const float4*)&Ws[kk][tx * 4];
            acc[0][0] += av.x * wv.x; acc[0][1] += av.x * wv.y;
            acc[0][2] += av.x * wv.z; acc[0][3] += av.x * wv.w;
            acc[1][0] += av.y * wv.x; acc[1][1] += av.y * wv.y;
            acc[1][2] += av.y * wv.z; acc[1][3] += av.y * wv.w;
            acc[2][0] += av.z * wv.x; acc[2][1] += av.z * wv.y;
            acc[2][2] += av.z * wv.z; acc[2][3] += av.z * wv.w;
            acc[3][0] += av.w * wv.x; acc[3][1] += av.w * wv.y;
            acc[3][2] += av.w * wv.z; acc[3][3] += av.w * wv.w;
        }
    }

#pragma unroll
    for (int i = 0; i < 4; i++) {
        const int m = m0 + ty * 4 + i;
#pragma unroll
        for (int j = 0; j < 4; j++) {
            const int n = n0 + tx * 4 + j;
            size_t idx;
            if (HEAD_LAYOUT) {
                const int b = m >> 11;          // m / 2048
                const int s = m & 2047;
                const int h = n >> 6;           // n / 64
                const int d = n & 63;
                idx = (((size_t)(b * NH + h) * S_) + s) * DH + d;
            } else {
                idx = (size_t)m * D_MODEL + n;
            }
            C[idx] = acc[i][j];
        }
    }
}

// ============================================================================
// Causal flash attention, fp32. One thread = one query row.
// Block: 128 threads handling 128 consecutive query rows of one (b,h).
// K/V staged in shared in 32-key tiles; online softmax with per-tile rescale.
// Q is pre-scaled by 1/sqrt(Dh). Output written in [B, S, H*Dh] token layout.
// ============================================================================
__global__ __launch_bounds__(128) void attn_kernel(
    const float* __restrict__ Q,
    const float* __restrict__ K,
    const float* __restrict__ V,
    float* __restrict__ O)
{
    __shared__ float Ks[32][64];
    __shared__ float Vs[32][64];

    const int tid = threadIdx.x;
    const int bh  = blockIdx.y;                 // 0..31
    const int qi  = blockIdx.x * 128 + tid;     // query row within head

    const float* qptr = Q + ((size_t)bh * S_ + qi) * DH;
    float q[DH];
#pragma unroll
    for (int d = 0; d < DH; d++) q[d] = qptr[d] * ATT_SCALE;

    float acc[DH];
#pragma unroll
    for (int d = 0; d < DH; d++) acc[d] = 0.f;
    float mrun = -1e30f;
    float lrun = 0.f;

    const int lr = tid >> 2;            // 0..31 key row to load
    const int lc = (tid & 3) * 16;      // 0,16,32,48

    const int ntiles = blockIdx.x * 4 + 4;   // covers keys 0 .. blk_end

    for (int t = 0; t < ntiles; t++) {
        const int krow0 = t * 32;
        __syncthreads();
        {
            const float* kp = K + ((size_t)bh * S_ + krow0 + lr) * DH + lc;
            const float* vp = V + ((size_t)bh * S_ + krow0 + lr) * DH + lc;
#pragma unroll
            for (int u = 0; u < 16; u += 4) {
                *(float4*)&Ks[lr][lc + u] = *(const float4*)(kp + u);
                *(float4*)&Vs[lr][lc + u] = *(const float4*)(vp + u);
            }
        }
        __syncthreads();

        if (krow0 <= qi) {
            float s[32];
            float tmax = -1e30f;
#pragma unroll
            for (int j = 0; j < 32; j++) {
                float dot = 0.f;
#pragma unroll
                for (int d = 0; d < DH; d++) dot += q[d] * Ks[j][d];
                s[j] = (krow0 + j <= qi) ? dot : -1e30f;
                tmax = fmaxf(tmax, s[j]);
            }
            const float mnew = fmaxf(mrun, tmax);
            const float corr = __expf(mrun - mnew);
            lrun *= corr;
#pragma unroll
            for (int d = 0; d < DH; d++) acc[d] *= corr;
#pragma unroll
            for (int j = 0; j < 32; j++) {
                const float p = __expf(s[j] - mnew);
                lrun += p;
#pragma unroll
                for (int d = 0; d < DH; d++) acc[d] += p * Vs[j][d];
            }
            mrun = mnew;
        }
    }

    const int b = bh / NH;
    const int h = bh % NH;
    const float inv = 1.f / lrun;
    float* op = O + ((size_t)(b * S_ + qi)) * D_MODEL + h * DH;
#pragma unroll
    for (int d = 0; d < DH; d++) op[d] = acc[d] * inv;
}

// ============================================================================
// launch
// ============================================================================
extern "C" void kernel_launch(void* const* d_in, const int* in_sizes, int n_in,
                              void* d_out, int out_size)
{
    const float* x  = (const float*)d_in[0];
    const float* Wq = (const float*)d_in[1];
    const float* Wk = (const float*)d_in[2];
    const float* Wv = (const float*)d_in[3];
    const float* Wo = (const float*)d_in[4];
    float* out = (float*)d_out;

    float *Qp, *Kp, *Vp, *Ap;
    cudaGetSymbolAddress((void**)&Qp, g_Q);
    cudaGetSymbolAddress((void**)&Kp, g_K);
    cudaGetSymbolAddress((void**)&Vp, g_V);
    cudaGetSymbolAddress((void**)&Ap, g_A);

    dim3 ggrid(D_MODEL / 64, M_TOK / 64);   // 16 x 64
    gemm_nt_kernel<true><<<ggrid, 256>>>(x, Wq, Qp);
    gemm_nt_kernel<true><<<ggrid, 256>>>(x, Wk, Kp);
    gemm_nt_kernel<true><<<ggrid, 256>>>(x, Wv, Vp);

    dim3 agrid(S_ / 128, B_ * NH);          // 16 x 32
    attn_kernel<<<agrid, 128>>>(Qp, Kp, Vp, Ap);

    gemm_nt_kernel<false><<<ggrid, 256>>>(Ap, Wo, out);
}

// round 3
// speedup vs baseline: 1.2535x; 1.2535x over previous
#include <cuda_runtime.h>
#include <cstdint>
#include <math.h>

#define D_MODEL 1024
#define NH      16
#define DH      64
#define B_      2
#define S_      2048
#define M_TOK   (B_ * S_)
#define ATT_SCALE 0.125f

// ---------------- scratch (allocation-free) ----------------
__device__ float g_Q[M_TOK * D_MODEL];
__device__ float g_K[M_TOK * D_MODEL];
__device__ float g_V[M_TOK * D_MODEL];
__device__ float g_A[M_TOK * D_MODEL];

// ---------------- helpers (portable PTX only: no tcgen05) ----------------
__device__ __forceinline__ uint32_t f2tf32(float f) {
    uint32_t u;
    asm("cvt.rna.tf32.f32 %0, %1;" : "=r"(u) : "f"(f));
    return u;
}

__device__ __forceinline__ void mma_tf32(float* c, const uint32_t* a, const uint32_t* b) {
    asm volatile(
        "mma.sync.aligned.m16n8k8.row.col.f32.tf32.tf32.f32 "
        "{%0,%1,%2,%3}, {%4,%5,%6,%7}, {%8,%9}, {%0,%1,%2,%3};"
        : "+f"(c[0]), "+f"(c[1]), "+f"(c[2]), "+f"(c[3])
        : "r"(a[0]), "r"(a[1]), "r"(a[2]), "r"(a[3]), "r"(b[0]), "r"(b[1]));
}

// ============================================================================
// tf32 mma.sync NT-GEMM: C[m][n] = sum_k A[m][k] * W[n][k]
// M=4096, N=K=1024. CTA 128x128 tile, 8 warps (4m x 2n), warp tile 32x64.
// K chunk 32, register-prefetched staging, smem stride 36 (conflict-free).
// ============================================================================
template <bool HEAD_LAYOUT>
__global__ __launch_bounds__(256) void gemm_mma_kernel(
    const float* __restrict__ A,
    const float* __restrict__ W,
    float* __restrict__ C)
{
    __shared__ float As[128][36];
    __shared__ float Bs[128][36];

    const int tid  = threadIdx.x;
    const int wid  = tid >> 5;
    const int lane = tid & 31;
    const int m0   = blockIdx.y * 128;
    const int n0   = blockIdx.x * 128;
    const int wm   = (wid & 3) * 32;    // warp m offset in tile
    const int wn   = (wid >> 2) * 64;   // warp n offset in tile

    // staging: each thread stages 4 float4 of A and of B per chunk
    const int lrow = tid >> 3;          // 0..31 (+t*32)
    const int lc4  = (tid & 7) * 4;     // 0..28

    const float* aptr = A + (size_t)(m0 + lrow) * D_MODEL + lc4;
    const float* wptr = W + (size_t)(n0 + lrow) * D_MODEL + lc4;

    float4 ar[4], br[4];

    float acc[2][8][4];
#pragma unroll
    for (int mt = 0; mt < 2; mt++)
#pragma unroll
        for (int nt = 0; nt < 8; nt++)
#pragma unroll
            for (int e = 0; e < 4; e++) acc[mt][nt][e] = 0.f;

    // prefetch chunk 0
#pragma unroll
    for (int t = 0; t < 4; t++) {
        ar[t] = *(const float4*)(aptr + (size_t)t * 32 * D_MODEL);
        br[t] = *(const float4*)(wptr + (size_t)t * 32 * D_MODEL);
    }

    for (int i = 0; i < D_MODEL / 32; i++) {
        __syncthreads();
        // store staged regs (converted to tf32 bits) into smem
#pragma unroll
        for (int t = 0; t < 4; t++) {
            const int row = lrow + t * 32;
            uint4 ua = make_uint4(f2tf32(ar[t].x), f2tf32(ar[t].y), f2tf32(ar[t].z), f2tf32(ar[t].w));
            uint4 ub = make_uint4(f2tf32(br[t].x), f2tf32(br[t].y), f2tf32(br[t].z), f2tf32(br[t].w));
            *(uint4*)&As[row][lc4] = ua;
            *(uint4*)&Bs[row][lc4] = ub;
        }
        __syncthreads();

        // prefetch next chunk
        if (i < D_MODEL / 32 - 1) {
            const int k0 = (i + 1) * 32;
#pragma unroll
            for (int t = 0; t < 4; t++) {
                ar[t] = *(const float4*)(aptr + (size_t)t * 32 * D_MODEL + k0);
                br[t] = *(const float4*)(wptr + (size_t)t * 32 * D_MODEL + k0);
            }
        }

        // compute: 4 k-steps of 8
#pragma unroll
        for (int ks = 0; ks < 4; ks++) {
            const int kb = ks * 8;
            const int fc = kb + (lane & 3);
            uint32_t a[2][4], b[8][2];
            const int fr = wm + (lane >> 2);
#pragma unroll
            for (int mt = 0; mt < 2; mt++) {
                const int r = fr + mt * 16;
                a[mt][0] = *(const uint32_t*)&As[r][fc];
                a[mt][1] = *(const uint32_t*)&As[r + 8][fc];
                a[mt][2] = *(const uint32_t*)&As[r][fc + 4];
                a[mt][3] = *(const uint32_t*)&As[r + 8][fc + 4];
            }
            const int bn = wn + (lane >> 2);
#pragma unroll
            for (int nt = 0; nt < 8; nt++) {
                b[nt][0] = *(const uint32_t*)&Bs[bn + nt * 8][fc];
                b[nt][1] = *(const uint32_t*)&Bs[bn + nt * 8][fc + 4];
            }
#pragma unroll
            for (int mt = 0; mt < 2; mt++)
#pragma unroll
                for (int nt = 0; nt < 8; nt++)
                    mma_tf32(acc[mt][nt], a[mt], b[nt]);
        }
    }

    // epilogue
    const int row  = lane >> 2;
    const int col2 = (lane & 3) * 2;
#pragma unroll
    for (int mt = 0; mt < 2; mt++) {
        const int m = m0 + wm + mt * 16 + row;
#pragma unroll
        for (int nt = 0; nt < 8; nt++) {
            const int n = n0 + wn + nt * 8 + col2;
            if (HEAD_LAYOUT) {
                const int b = m >> 11, s = m & 2047, h = n >> 6, d = n & 63;
                float* dst = C + (((size_t)(b * NH + h) * S_) + s) * DH + d;
                *(float2*)dst = make_float2(acc[mt][nt][0], acc[mt][nt][1]);
                float* dst2 = C + (((size_t)(b * NH + h) * S_) + s + 8) * DH + d;
                *(float2*)dst2 = make_float2(acc[mt][nt][2], acc[mt][nt][3]);
            } else {
                float* dst = C + (size_t)m * D_MODEL + n;
                *(float2*)dst = make_float2(acc[mt][nt][0], acc[mt][nt][1]);
                *(float2*)(dst + 8 * D_MODEL) = make_float2(acc[mt][nt][2], acc[mt][nt][3]);
            }
        }
    }
}

// ============================================================================
// Causal flash attention, fp32, 2 threads per query (each owns 32 dims).
// 256 threads = 128 queries per CTA. Dots combined via shfl.xor(1).
// Warp-uniform causal branch; per-key masking inside. launch_bounds(256,2)
// caps regs at 128 -> 2 CTAs/SM (16 warps, ~3x R1 occupancy).
// ============================================================================
__global__ __launch_bounds__(256, 2) void attn_kernel(
    const float* __restrict__ Q,
    const float* __restrict__ K,
    const float* __restrict__ V,
    float* __restrict__ O)
{
    __shared__ float Ks[32][64];
    __shared__ float Vs[32][64];

    const int tid  = threadIdx.x;
    const int bh   = blockIdx.y;
    const int qloc = tid >> 1;
    const int qi   = blockIdx.x * 128 + qloc;
    const int half = tid & 1;
    // max query handled by this warp (16 queries per warp) -> uniform branches
    const int qwmax = blockIdx.x * 128 + (tid >> 5) * 16 + 15;

    const float* qptr = Q + ((size_t)bh * S_ + qi) * DH + half * 32;
    float q[32];
#pragma unroll
    for (int d = 0; d < 32; d++) q[d] = qptr[d] * ATT_SCALE;

    float acc[32];
#pragma unroll
    for (int d = 0; d < 32; d++) acc[d] = 0.f;
    float mrun = -1e30f;
    float lrun = 0.f;

    const int lr = tid >> 3;         // 0..31 key row to load
    const int lc = (tid & 7) * 8;    // 0..56
    const int ntiles = blockIdx.x * 4 + 4;

    for (int t = 0; t < ntiles; t++) {
        const int krow0 = t * 32;
        __syncthreads();
        {
            const float* kp = K + ((size_t)bh * S_ + krow0 + lr) * DH + lc;
            const float* vp = V + ((size_t)bh * S_ + krow0 + lr) * DH + lc;
            *(float4*)&Ks[lr][lc]     = *(const float4*)kp;
            *(float4*)&Ks[lr][lc + 4] = *(const float4*)(kp + 4);
            *(float4*)&Vs[lr][lc]     = *(const float4*)vp;
            *(float4*)&Vs[lr][lc + 4] = *(const float4*)(vp + 4);
        }
        __syncthreads();

        if (krow0 <= qwmax) {
#pragma unroll
            for (int st = 0; st < 2; st++) {
                const int kb = krow0 + st * 16;
                if (kb <= qwmax) {   // warp-uniform
                    float s[16];
                    float tmax = -1e30f;
#pragma unroll
                    for (int j = 0; j < 16; j++) {
                        float dot = 0.f;
#pragma unroll
                        for (int d = 0; d < 32; d++)
                            dot += q[d] * Ks[st * 16 + j][half * 32 + d];
                        dot += __shfl_xor_sync(0xffffffffu, dot, 1);
                        s[j] = (kb + j <= qi) ? dot : -1e30f;
                        tmax = fmaxf(tmax, s[j]);
                    }
                    const float mnew = fmaxf(mrun, tmax);
                    const float corr = __expf(mrun - mnew);
                    lrun *= corr;
#pragma unroll
                    for (int d = 0; d < 32; d++) acc[d] *= corr;
#pragma unroll
                    for (int j = 0; j < 16; j++) {
                        const float p = __expf(s[j] - mnew);
                        lrun += p;
#pragma unroll
                        for (int d = 0; d < 32; d++)
                            acc[d] += p * Vs[st * 16 + j][half * 32 + d];
                    }
                    mrun = mnew;
                }
            }
        }
    }

    const int b = bh / NH;
    const int h = bh % NH;
    const float inv = 1.f / lrun;
    float* op = O + ((size_t)(b * S_ + qi)) * D_MODEL + h * DH + half * 32;
#pragma unroll
    for (int d = 0; d < 32; d++) op[d] = acc[d] * inv;
}

// ============================================================================
// launch
// ============================================================================
extern "C" void kernel_launch(void* const* d_in, const int* in_sizes, int n_in,
                              void* d_out, int out_size)
{
    const float* x  = (const float*)d_in[0];
    const float* Wq = (const float*)d_in[1];
    const float* Wk = (const float*)d_in[2];
    const float* Wv = (const float*)d_in[3];
    const float* Wo = (const float*)d_in[4];
    float* out = (float*)d_out;

    float *Qp, *Kp, *Vp, *Ap;
    cudaGetSymbolAddress((void**)&Qp, g_Q);
    cudaGetSymbolAddress((void**)&Kp, g_K);
    cudaGetSymbolAddress((void**)&Vp, g_V);
    cudaGetSymbolAddress((void**)&Ap, g_A);

    dim3 ggrid(D_MODEL / 128, M_TOK / 128);   // 8 x 32 = 256 CTAs
    gemm_mma_kernel<true><<<ggrid, 256>>>(x, Wq, Qp);
    gemm_mma_kernel<true><<<ggrid, 256>>>(x, Wk, Kp);
    gemm_mma_kernel<true><<<ggrid, 256>>>(x, Wv, Vp);

    dim3 agrid(S_ / 128, B_ * NH);            // 16 x 32
    attn_kernel<<<agrid, 256>>>(Qp, Kp, Vp, Ap);

    gemm_mma_kernel<false><<<ggrid, 256>>>(Ap, Wo, out);
}

// round 4
// speedup vs baseline: 4.3338x; 3.4574x over previous
#include <cuda_runtime.h>
#include <cstdint>
#include <math.h>

#define D_MODEL 1024
#define NH      16
#define DH      64
#define B_      2
#define S_      2048
#define M_TOK   (B_ * S_)
#define ATT_SCALE 0.125f

// ---------------- scratch (allocation-free) ----------------
__device__ float g_Q[M_TOK * D_MODEL];
__device__ float g_K[M_TOK * D_MODEL];
__device__ float g_V[M_TOK * D_MODEL];
__device__ float g_A[M_TOK * D_MODEL];

// ---------------- helpers (portable PTX only: no tcgen05) ----------------
__device__ __forceinline__ uint32_t f2tf32(float f) {
    uint32_t u;
    asm("cvt.rna.tf32.f32 %0, %1;" : "=r"(u) : "f"(f));
    return u;
}

__device__ __forceinline__ void mma_tf32(float* c, const uint32_t* a, const uint32_t* b) {
    asm volatile(
        "mma.sync.aligned.m16n8k8.row.col.f32.tf32.tf32.f32 "
        "{%0,%1,%2,%3}, {%4,%5,%6,%7}, {%8,%9}, {%0,%1,%2,%3};"
        : "+f"(c[0]), "+f"(c[1]), "+f"(c[2]), "+f"(c[3])
        : "r"(a[0]), "r"(a[1]), "r"(a[2]), "r"(a[3]), "r"(b[0]), "r"(b[1]));
}

// ============================================================================
// tf32 mma.sync NT-GEMM (unchanged from R3): C[m][n] = sum_k A[m][k]*W[n][k]
// ============================================================================
template <bool HEAD_LAYOUT>
__global__ __launch_bounds__(256) void gemm_mma_kernel(
    const float* __restrict__ A,
    const float* __restrict__ W,
    float* __restrict__ C)
{
    __shared__ float As[128][36];
    __shared__ float Bs[128][36];

    const int tid  = threadIdx.x;
    const int wid  = tid >> 5;
    const int lane = tid & 31;
    const int m0   = blockIdx.y * 128;
    const int n0   = blockIdx.x * 128;
    const int wm   = (wid & 3) * 32;
    const int wn   = (wid >> 2) * 64;

    const int lrow = tid >> 3;
    const int lc4  = (tid & 7) * 4;

    const float* aptr = A + (size_t)(m0 + lrow) * D_MODEL + lc4;
    const float* wptr = W + (size_t)(n0 + lrow) * D_MODEL + lc4;

    float4 ar[4], br[4];

    float acc[2][8][4];
#pragma unroll
    for (int mt = 0; mt < 2; mt++)
#pragma unroll
        for (int nt = 0; nt < 8; nt++)
#pragma unroll
            for (int e = 0; e < 4; e++) acc[mt][nt][e] = 0.f;

#pragma unroll
    for (int t = 0; t < 4; t++) {
        ar[t] = *(const float4*)(aptr + (size_t)t * 32 * D_MODEL);
        br[t] = *(const float4*)(wptr + (size_t)t * 32 * D_MODEL);
    }

    for (int i = 0; i < D_MODEL / 32; i++) {
        __syncthreads();
#pragma unroll
        for (int t = 0; t < 4; t++) {
            const int row = lrow + t * 32;
            uint4 ua = make_uint4(f2tf32(ar[t].x), f2tf32(ar[t].y), f2tf32(ar[t].z), f2tf32(ar[t].w));
            uint4 ub = make_uint4(f2tf32(br[t].x), f2tf32(br[t].y), f2tf32(br[t].z), f2tf32(br[t].w));
            *(uint4*)&As[row][lc4] = ua;
            *(uint4*)&Bs[row][lc4] = ub;
        }
        __syncthreads();

        if (i < D_MODEL / 32 - 1) {
            const int k0 = (i + 1) * 32;
#pragma unroll
            for (int t = 0; t < 4; t++) {
                ar[t] = *(const float4*)(aptr + (size_t)t * 32 * D_MODEL + k0);
                br[t] = *(const float4*)(wptr + (size_t)t * 32 * D_MODEL + k0);
            }
        }

#pragma unroll
        for (int ks = 0; ks < 4; ks++) {
            const int kb = ks * 8;
            const int fc = kb + (lane & 3);
            uint32_t a[2][4], b[8][2];
            const int fr = wm + (lane >> 2);
#pragma unroll
            for (int mt = 0; mt < 2; mt++) {
                const int r = fr + mt * 16;
                a[mt][0] = *(const uint32_t*)&As[r][fc];
                a[mt][1] = *(const uint32_t*)&As[r + 8][fc];
                a[mt][2] = *(const uint32_t*)&As[r][fc + 4];
                a[mt][3] = *(const uint32_t*)&As[r + 8][fc + 4];
            }
            const int bn = wn + (lane >> 2);
#pragma unroll
            for (int nt = 0; nt < 8; nt++) {
                b[nt][0] = *(const uint32_t*)&Bs[bn + nt * 8][fc];
                b[nt][1] = *(const uint32_t*)&Bs[bn + nt * 8][fc + 4];
            }
#pragma unroll
            for (int mt = 0; mt < 2; mt++)
#pragma unroll
                for (int nt = 0; nt < 8; nt++)
                    mma_tf32(acc[mt][nt], a[mt], b[nt]);
        }
    }

    const int row  = lane >> 2;
    const int col2 = (lane & 3) * 2;
#pragma unroll
    for (int mt = 0; mt < 2; mt++) {
        const int m = m0 + wm + mt * 16 + row;
#pragma unroll
        for (int nt = 0; nt < 8; nt++) {
            const int n = n0 + wn + nt * 8 + col2;
            if (HEAD_LAYOUT) {
                const int b = m >> 11, s = m & 2047, h = n >> 6, d = n & 63;
                float* dst = C + (((size_t)(b * NH + h) * S_) + s) * DH + d;
                *(float2*)dst = make_float2(acc[mt][nt][0], acc[mt][nt][1]);
                float* dst2 = C + (((size_t)(b * NH + h) * S_) + s + 8) * DH + d;
                *(float2*)dst2 = make_float2(acc[mt][nt][2], acc[mt][nt][3]);
            } else {
                float* dst = C + (size_t)m * D_MODEL + n;
                *(float2*)dst = make_float2(acc[mt][nt][0], acc[mt][nt][1]);
                *(float2*)(dst + 8 * D_MODEL) = make_float2(acc[mt][nt][2], acc[mt][nt][3]);
            }
        }
    }
}

// ============================================================================
// Tensor-core causal flash attention (tf32 mma.sync).
// CTA: 128 queries, 8 warps x 16 rows; 32-key tiles.
// QK^T: Q frags in regs, K k-major smem (stride 68 -> conflict-free).
// softmax on C-fragments (quad shfl reductions), P via per-warp smem.
// PV: V transposed in smem (stride 36 -> conflict-free).
// ============================================================================
__global__ __launch_bounds__(256, 2) void attn_mma_kernel(
    const float* __restrict__ Q,
    const float* __restrict__ K,
    const float* __restrict__ V,
    float* __restrict__ O)
{
    __shared__ uint32_t Ks[32][68];        // [key][dim]  (tf32 bits)
    __shared__ uint32_t Vt[64][36];        // [dim][key]  (tf32 bits)
    __shared__ uint32_t Ps[8][16][36];     // per-warp P  (tf32 bits)

    const int tid  = threadIdx.x;
    const int wid  = tid >> 5;
    const int lane = tid & 31;
    const int gid  = lane >> 2;            // 0..7
    const int tig  = lane & 3;             // 0..3
    const int bh   = blockIdx.y;
    const int q0   = blockIdx.x * 128;
    const int qr0  = q0 + wid * 16;        // warp's first query row

    // ---- load Q fragments (once), pre-scaled ----
    const float* Qb = Q + ((size_t)bh * S_ + qr0) * DH;
    uint32_t qa[8][4];
#pragma unroll
    for (int ks = 0; ks < 8; ks++) {
        const int col = ks * 8 + tig;
        qa[ks][0] = f2tf32(Qb[(size_t)gid * DH + col] * ATT_SCALE);
        qa[ks][1] = f2tf32(Qb[(size_t)(gid + 8) * DH + col] * ATT_SCALE);
        qa[ks][2] = f2tf32(Qb[(size_t)gid * DH + col + 4] * ATT_SCALE);
        qa[ks][3] = f2tf32(Qb[(size_t)(gid + 8) * DH + col + 4] * ATT_SCALE);
    }

    float o[8][4];
#pragma unroll
    for (int dt = 0; dt < 8; dt++)
#pragma unroll
        for (int e = 0; e < 4; e++) o[dt][e] = 0.f;
    float mr0 = -1e30f, mr1 = -1e30f;
    float lr0 = 0.f, lr1 = 0.f;

    const int ntiles = blockIdx.x * 4 + 4;

    for (int t = 0; t < ntiles; t++) {
        const int krow0 = t * 32;
        __syncthreads();

        // ---- stage K tile (k-major) ----
#pragma unroll
        for (int it = 0; it < 2; it++) {
            const int f   = tid + it * 256;
            const int key = f >> 4;
            const int c4  = (f & 15) * 4;
            float4 v = *(const float4*)(K + ((size_t)bh * S_ + krow0 + key) * DH + c4);
            uint4 u = make_uint4(f2tf32(v.x), f2tf32(v.y), f2tf32(v.z), f2tf32(v.w));
            *(uint4*)&Ks[key][c4] = u;
        }
        // ---- stage V tile transposed ----
        {
            const int key = tid & 31;
            const int d0  = (tid >> 5) * 8;
            const float* vp = V + ((size_t)bh * S_ + krow0 + key) * DH + d0;
            float4 v0 = *(const float4*)vp;
            float4 v1 = *(const float4*)(vp + 4);
            Vt[d0 + 0][key] = f2tf32(v0.x); Vt[d0 + 1][key] = f2tf32(v0.y);
            Vt[d0 + 2][key] = f2tf32(v0.z); Vt[d0 + 3][key] = f2tf32(v0.w);
            Vt[d0 + 4][key] = f2tf32(v1.x); Vt[d0 + 5][key] = f2tf32(v1.y);
            Vt[d0 + 6][key] = f2tf32(v1.z); Vt[d0 + 7][key] = f2tf32(v1.w);
        }
        __syncthreads();

        if (krow0 > qr0 + 15) continue;   // warp-uniform causal skip

        // ---- S = Q K^T  (16 x 32 per warp) ----
        float sc[4][4];
#pragma unroll
        for (int nt = 0; nt < 4; nt++)
#pragma unroll
            for (int e = 0; e < 4; e++) sc[nt][e] = 0.f;
#pragma unroll
        for (int ks = 0; ks < 8; ks++) {
            const int fc = ks * 8 + tig;
#pragma unroll
            for (int nt = 0; nt < 4; nt++) {
                uint32_t b[2];
                b[0] = Ks[nt * 8 + gid][fc];
                b[1] = Ks[nt * 8 + gid][fc + 4];
                mma_tf32(sc[nt], qa[ks], b);
            }
        }

        // ---- causal mask (diagonal tiles only) ----
        const int row0 = qr0 + gid;
        const int row1 = qr0 + 8 + gid;
        if (krow0 + 31 > qr0) {
#pragma unroll
            for (int nt = 0; nt < 4; nt++) {
                const int kc = krow0 + nt * 8 + 2 * tig;
                if (kc > row0)     sc[nt][0] = -1e30f;
                if (kc + 1 > row0) sc[nt][1] = -1e30f;
                if (kc > row1)     sc[nt][2] = -1e30f;
                if (kc + 1 > row1) sc[nt][3] = -1e30f;
            }
        }

        // ---- online softmax on fragments ----
        float tmax0 = -1e30f, tmax1 = -1e30f;
#pragma unroll
        for (int nt = 0; nt < 4; nt++) {
            tmax0 = fmaxf(tmax0, fmaxf(sc[nt][0], sc[nt][1]));
            tmax1 = fmaxf(tmax1, fmaxf(sc[nt][2], sc[nt][3]));
        }
        tmax0 = fmaxf(tmax0, __shfl_xor_sync(0xffffffffu, tmax0, 1));
        tmax0 = fmaxf(tmax0, __shfl_xor_sync(0xffffffffu, tmax0, 2));
        tmax1 = fmaxf(tmax1, __shfl_xor_sync(0xffffffffu, tmax1, 1));
        tmax1 = fmaxf(tmax1, __shfl_xor_sync(0xffffffffu, tmax1, 2));

        const float mn0 = fmaxf(mr0, tmax0);
        const float mn1 = fmaxf(mr1, tmax1);
        const float cr0 = __expf(mr0 - mn0);
        const float cr1 = __expf(mr1 - mn1);

        float sum0 = 0.f, sum1 = 0.f;
#pragma unroll
        for (int nt = 0; nt < 4; nt++) {
            float p0 = __expf(sc[nt][0] - mn0);
            float p1 = __expf(sc[nt][1] - mn0);
            float p2 = __expf(sc[nt][2] - mn1);
            float p3 = __expf(sc[nt][3] - mn1);
            sum0 += p0 + p1;
            sum1 += p2 + p3;
            const int col = nt * 8 + 2 * tig;
            *(uint2*)&Ps[wid][gid][col]     = make_uint2(f2tf32(p0), f2tf32(p1));
            *(uint2*)&Ps[wid][gid + 8][col] = make_uint2(f2tf32(p2), f2tf32(p3));
        }
        sum0 += __shfl_xor_sync(0xffffffffu, sum0, 1);
        sum0 += __shfl_xor_sync(0xffffffffu, sum0, 2);
        sum1 += __shfl_xor_sync(0xffffffffu, sum1, 1);
        sum1 += __shfl_xor_sync(0xffffffffu, sum1, 2);

        lr0 = lr0 * cr0 + sum0;
        lr1 = lr1 * cr1 + sum1;
#pragma unroll
        for (int dt = 0; dt < 8; dt++) {
            o[dt][0] *= cr0; o[dt][1] *= cr0;
            o[dt][2] *= cr1; o[dt][3] *= cr1;
        }
        mr0 = mn0; mr1 = mn1;
        __syncwarp();

        // ---- O += P V ----
#pragma unroll
        for (int ks2 = 0; ks2 < 4; ks2++) {
            const int kc = ks2 * 8 + tig;
            uint32_t pa[4];
            pa[0] = Ps[wid][gid][kc];
            pa[1] = Ps[wid][gid + 8][kc];
            pa[2] = Ps[wid][gid][kc + 4];
            pa[3] = Ps[wid][gid + 8][kc + 4];
#pragma unroll
            for (int dt = 0; dt < 8; dt++) {
                uint32_t b[2];
                b[0] = Vt[dt * 8 + gid][kc];
                b[1] = Vt[dt * 8 + gid][kc + 4];
                mma_tf32(o[dt], pa, b);
            }
        }
        __syncwarp();
    }

    // ---- epilogue: write token-layout output ----
    const int b  = bh / NH;
    const int h  = bh % NH;
    const float inv0 = 1.f / lr0;
    const float inv1 = 1.f / lr1;
    const int row0 = qr0 + gid;
    const int row1 = qr0 + 8 + gid;
    float* op0 = O + ((size_t)(b * S_ + row0)) * D_MODEL + h * DH;
    float* op1 = O + ((size_t)(b * S_ + row1)) * D_MODEL + h * DH;
#pragma unroll
    for (int dt = 0; dt < 8; dt++) {
        const int d = dt * 8 + 2 * tig;
        *(float2*)(op0 + d) = make_float2(o[dt][0] * inv0, o[dt][1] * inv0);
        *(float2*)(op1 + d) = make_float2(o[dt][2] * inv1, o[dt][3] * inv1);
    }
}

// ============================================================================
// launch
// ============================================================================
extern "C" void kernel_launch(void* const* d_in, const int* in_sizes, int n_in,
                              void* d_out, int out_size)
{
    const float* x  = (const float*)d_in[0];
    const float* Wq = (const float*)d_in[1];
    const float* Wk = (const float*)d_in[2];
    const float* Wv = (const float*)d_in[3];
    const float* Wo = (const float*)d_in[4];
    float* out = (float*)d_out;

    float *Qp, *Kp, *Vp, *Ap;
    cudaGetSymbolAddress((void**)&Qp, g_Q);
    cudaGetSymbolAddress((void**)&Kp, g_K);
    cudaGetSymbolAddress((void**)&Vp, g_V);
    cudaGetSymbolAddress((void**)&Ap, g_A);

    dim3 ggrid(D_MODEL / 128, M_TOK / 128);   // 8 x 32 = 256 CTAs
    gemm_mma_kernel<true><<<ggrid, 256>>>(x, Wq, Qp);
    gemm_mma_kernel<true><<<ggrid, 256>>>(x, Wk, Kp);
    gemm_mma_kernel<true><<<ggrid, 256>>>(x, Wv, Vp);

    dim3 agrid(S_ / 128, B_ * NH);            // 16 x 32
    attn_mma_kernel<<<agrid, 256>>>(Qp, Kp, Vp, Ap);

    gemm_mma_kernel<false><<<ggrid, 256>>>(Ap, Wo, out);
}